// round 12
// baseline (speedup 1.0000x reference)
#include <cuda_runtime.h>
#include <cuda_bf16.h>
#include <math_constants.h>
#include <cstdint>

// Problem constants
#define BATCH   2
#define SEQ     2048
#define T_TOK   4096
#define DMODEL  1024
#define PROJ    256
#define HEADS   16
#define DH      64

// ---------------------------------------------------------------------------
// Scratch (device globals)
// ---------------------------------------------------------------------------
__device__ uint32_t g_xh  [T_TOK * DMODEL / 2];
__device__ uint32_t g_xl  [T_TOK * DMODEL / 2];
__device__ uint32_t g_wdqh[PROJ * DMODEL / 2],  g_wdql[PROJ * DMODEL / 2];
__device__ uint32_t g_wdkh[PROJ * DMODEL / 2],  g_wdkl[PROJ * DMODEL / 2];
__device__ uint32_t g_wuqh[DMODEL * PROJ / 2],  g_wuql[DMODEL * PROJ / 2];
__device__ uint32_t g_wukh[2 * DMODEL * PROJ / 2], g_wukl[2 * DMODEL * PROJ / 2];
__device__ uint32_t g_woh [DMODEL * DMODEL / 2], g_wol [DMODEL * DMODEL / 2];
__device__ float    g_cq  [T_TOK * PROJ];
__device__ float    g_ckv [T_TOK * PROJ];
__device__ uint32_t g_cqph[T_TOK * PROJ / 2],  g_cqpl[T_TOK * PROJ / 2];
__device__ uint32_t g_ckph[T_TOK * PROJ / 2],  g_ckpl[T_TOK * PROJ / 2];
__device__ uint32_t g_qph [T_TOK * DMODEL / 2], g_qpl [T_TOK * DMODEL / 2];
__device__ uint32_t g_kvh [T_TOK * DMODEL],     g_kvl [T_TOK * DMODEL];
__device__ uint32_t g_aoh [T_TOK * DMODEL / 2], g_aol [T_TOK * DMODEL / 2];

// ---------------------------------------------------------------------------
// Helpers
// ---------------------------------------------------------------------------
__device__ __forceinline__ void cvt_hilo2(float x, float y, uint32_t& h, uint32_t& l)
{
    __nv_bfloat162 hv = __floats2bfloat162_rn(x, y);   // .x = low half
    float rx = x - __bfloat162float(hv.x);
    float ry = y - __bfloat162float(hv.y);
    __nv_bfloat162 lv = __floats2bfloat162_rn(rx, ry);
    h = *(uint32_t*)&hv;
    l = *(uint32_t*)&lv;
}

__device__ __forceinline__ void mma16816(float* c, uint32_t a0, uint32_t a1,
                                         uint32_t a2, uint32_t a3,
                                         uint32_t b0, uint32_t b1)
{
    asm volatile(
        "mma.sync.aligned.m16n8k16.row.col.f32.bf16.bf16.f32 "
        "{%0,%1,%2,%3}, {%4,%5,%6,%7}, {%8,%9}, {%0,%1,%2,%3};\n"
        : "+f"(c[0]), "+f"(c[1]), "+f"(c[2]), "+f"(c[3])
        : "r"(a0), "r"(a1), "r"(a2), "r"(a3), "r"(b0), "r"(b1));
}

__device__ __forceinline__ void ldsm_x4(uint32_t& r0, uint32_t& r1,
                                        uint32_t& r2, uint32_t& r3, uint32_t addr)
{
    asm volatile("ldmatrix.sync.aligned.m8n8.x4.shared.b16 {%0,%1,%2,%3}, [%4];"
                 : "=r"(r0), "=r"(r1), "=r"(r2), "=r"(r3) : "r"(addr));
}

__device__ __forceinline__ uint32_t smem_addr(const void* p)
{
    return (uint32_t)__cvta_generic_to_shared(p);
}

// ---------------------------------------------------------------------------
// Pack kernels
// ---------------------------------------------------------------------------
__global__ __launch_bounds__(256) void pack_hilo(
    const float* __restrict__ X, uint32_t* __restrict__ H,
    uint32_t* __restrict__ L, int nwords)
{
    const int i = blockIdx.x * 256 + threadIdx.x;
    if (i >= nwords) return;
    float2 v = ((const float2*)X)[i];
    uint32_t h, l;
    cvt_hilo2(v.x, v.y, h, l);
    H[i] = h; L[i] = l;
}

// W [K][N] row-major -> H/L [N][K/2] words (transpose + pack along K)
__global__ __launch_bounds__(256) void pack_hilo_t(
    const float* __restrict__ W, uint32_t* __restrict__ H,
    uint32_t* __restrict__ L, int N, int Kw)
{
    const int idx = blockIdx.x * 256 + threadIdx.x;
    if (idx >= N * Kw) return;
    const int kw = idx / N;
    const int n  = idx - kw * N;
    float a = W[(size_t)(2 * kw) * N + n];
    float b = W[(size_t)(2 * kw + 1) * N + n];
    uint32_t h, l;
    cvt_hilo2(a, b, h, l);
    H[(size_t)n * Kw + kw] = h;
    L[(size_t)n * Kw + kw] = l;
}

// ============================================================================
// gemm_bf: C = (Ah+Al)[M,K] @ (Bh+Bl)^T, pre-packed hi/lo words along K.
// Tile 128x128, K-chunk 32 (16 words), 256 threads, 2-stage smem pipeline.
// Dual-side: blocks bx < halfx use side-0 operands, else side-1.
// pout=1: epilogue writes packed hi/lo words instead of fp32.
// ============================================================================
#define GSTR 20
#define SSTG (4 * 128 * GSTR)            // words per stage (4 arrays)
#define GEMM_SMEM (2 * SSTG * 4)         // bytes

__global__ __launch_bounds__(256) void gemm_bf(
    const uint32_t* __restrict__ A0h, const uint32_t* __restrict__ A0l,
    const uint32_t* __restrict__ A1h, const uint32_t* __restrict__ A1l,
    const uint32_t* __restrict__ B0h, const uint32_t* __restrict__ B0l,
    const uint32_t* __restrict__ B1h, const uint32_t* __restrict__ B1l,
    float* __restrict__ C0, float* __restrict__ C1,
    uint32_t* __restrict__ H0, uint32_t* __restrict__ L0,
    uint32_t* __restrict__ H1, uint32_t* __restrict__ L1,
    int N0, int N1, int Kw, int halfx, int pout)
{
    extern __shared__ uint32_t sm[];

    const int tid  = threadIdx.x;
    const int warp = tid >> 5, lane = tid & 31;
    const int g = lane >> 2, t = lane & 3;
    const int mi = (warp & 1) * 64;
    const int ni = (warp >> 1) * 32;

    const bool s1 = blockIdx.x >= halfx;
    const uint32_t* Ah = s1 ? A1h : A0h;
    const uint32_t* Al = s1 ? A1l : A0l;
    const uint32_t* Bh = s1 ? B1h : B0h;
    const uint32_t* Bl = s1 ? B1l : B0l;
    float* C = s1 ? C1 : C0;
    uint32_t* H = s1 ? H1 : H0;
    uint32_t* L = s1 ? L1 : L0;
    const int N = s1 ? N1 : N0;
    const int bn = (blockIdx.x - (s1 ? halfx : 0)) * 128;
    const int bm = blockIdx.y * 128;

    const int r0s = tid >> 2, s0s = tid & 3;
    const int r1s = (256 + tid) >> 2, s1s = (256 + tid) & 3;

    const uint32_t* pAh = Ah + (size_t)bm * Kw;
    const uint32_t* pAl = Al + (size_t)bm * Kw;
    const uint32_t* pBh = Bh + (size_t)bn * Kw;
    const uint32_t* pBl = Bl + (size_t)bn * Kw;

    // ldmatrix per-lane base byte offsets (stage 0)
    const int rowA = mi + (lane & 15);
    const int colA = (lane >> 4) * 4;
    const uint32_t offA = (uint32_t)(rowA * GSTR + colA) * 4u;
    const int rowB = ni + (lane & 7) + ((lane >> 4) * 8);
    const int colB = ((lane >> 3) & 1) * 4;
    const uint32_t offB = (uint32_t)(rowB * GSTR + colB) * 4u;
    const uint32_t base = smem_addr(sm);
    const uint32_t aAh0 = base + offA;
    const uint32_t aAl0 = base + 2560u * 4u + offA;
    const uint32_t aBh0 = base + 5120u * 4u + offB;
    const uint32_t aBl0 = base + 7680u * 4u + offB;

    uint4 rg[8];
    auto load_chunk = [&](int c) {
        const int kb = c * 16;
        rg[0] = *(const uint4*)&pAh[(size_t)r0s * Kw + kb + s0s * 4];
        rg[1] = *(const uint4*)&pAh[(size_t)r1s * Kw + kb + s1s * 4];
        rg[2] = *(const uint4*)&pAl[(size_t)r0s * Kw + kb + s0s * 4];
        rg[3] = *(const uint4*)&pAl[(size_t)r1s * Kw + kb + s1s * 4];
        rg[4] = *(const uint4*)&pBh[(size_t)r0s * Kw + kb + s0s * 4];
        rg[5] = *(const uint4*)&pBh[(size_t)r1s * Kw + kb + s1s * 4];
        rg[6] = *(const uint4*)&pBl[(size_t)r0s * Kw + kb + s0s * 4];
        rg[7] = *(const uint4*)&pBl[(size_t)r1s * Kw + kb + s1s * 4];
    };
    auto store_chunk = [&](int st) {
        uint32_t* ss = sm + st * SSTG;
        *(uint4*)&ss[r0s * GSTR + s0s * 4] = rg[0];
        *(uint4*)&ss[r1s * GSTR + s1s * 4] = rg[1];
        *(uint4*)&ss[2560 + r0s * GSTR + s0s * 4] = rg[2];
        *(uint4*)&ss[2560 + r1s * GSTR + s1s * 4] = rg[3];
        *(uint4*)&ss[5120 + r0s * GSTR + s0s * 4] = rg[4];
        *(uint4*)&ss[5120 + r1s * GSTR + s1s * 4] = rg[5];
        *(uint4*)&ss[7680 + r0s * GSTR + s0s * 4] = rg[6];
        *(uint4*)&ss[7680 + r1s * GSTR + s1s * 4] = rg[7];
    };

    float acc[4][4][4] = {};

    const int nch = Kw / 16;
    load_chunk(0);
    store_chunk(0);
    __syncthreads();

    for (int c = 0; c < nch; c++) {
        const int st = c & 1;
        const uint32_t stoff = (uint32_t)st * (SSTG * 4u);
        if (c + 1 < nch) load_chunk(c + 1);

#pragma unroll
        for (int k2 = 0; k2 < 2; k2++) {
            const uint32_t koff = (uint32_t)(k2 * 8) * 4u + stoff;
            uint32_t afh[4][4], afl[4][4];
#pragma unroll
            for (int fm = 0; fm < 4; fm++) {
                const uint32_t fo = (uint32_t)(fm * 16 * GSTR) * 4u + koff;
                ldsm_x4(afh[fm][0], afh[fm][1], afh[fm][2], afh[fm][3], aAh0 + fo);
                ldsm_x4(afl[fm][0], afl[fm][1], afl[fm][2], afl[fm][3], aAl0 + fo);
            }
            uint32_t bfh[4][2], bfl[4][2];
#pragma unroll
            for (int fnp = 0; fnp < 2; fnp++) {
                const uint32_t fo = (uint32_t)(fnp * 16 * GSTR) * 4u + koff;
                ldsm_x4(bfh[2 * fnp][0], bfh[2 * fnp][1],
                        bfh[2 * fnp + 1][0], bfh[2 * fnp + 1][1], aBh0 + fo);
                ldsm_x4(bfl[2 * fnp][0], bfl[2 * fnp][1],
                        bfl[2 * fnp + 1][0], bfl[2 * fnp + 1][1], aBl0 + fo);
            }
#pragma unroll
            for (int fm = 0; fm < 4; fm++)
#pragma unroll
                for (int fn = 0; fn < 4; fn++) {
                    mma16816(acc[fm][fn], afh[fm][0], afh[fm][1],
                             afh[fm][2], afh[fm][3], bfh[fn][0], bfh[fn][1]);
                    mma16816(acc[fm][fn], afh[fm][0], afh[fm][1],
                             afh[fm][2], afh[fm][3], bfl[fn][0], bfl[fn][1]);
                    mma16816(acc[fm][fn], afl[fm][0], afl[fm][1],
                             afl[fm][2], afl[fm][3], bfh[fn][0], bfh[fn][1]);
                }
        }

        if (c + 1 < nch) store_chunk(st ^ 1);
        __syncthreads();
    }

    if (pout) {
        const int Nw = N >> 1;
#pragma unroll
        for (int fm = 0; fm < 4; fm++) {
            const int row = bm + mi + fm * 16 + g;
#pragma unroll
            for (int fn = 0; fn < 4; fn++) {
                const int wi = (bn + ni + fn * 8) / 2 + t;
                uint32_t hh, ll;
                cvt_hilo2(acc[fm][fn][0], acc[fm][fn][1], hh, ll);
                H[(size_t)row * Nw + wi] = hh;
                L[(size_t)row * Nw + wi] = ll;
                cvt_hilo2(acc[fm][fn][2], acc[fm][fn][3], hh, ll);
                H[(size_t)(row + 8) * Nw + wi] = hh;
                L[(size_t)(row + 8) * Nw + wi] = ll;
            }
        }
    } else {
#pragma unroll
        for (int fm = 0; fm < 4; fm++) {
            const int row = bm + mi + fm * 16 + g;
#pragma unroll
            for (int fn = 0; fn < 4; fn++) {
                const int col = bn + ni + fn * 8 + t * 2;
                *(float2*)&C[(size_t)row * N + col] =
                    make_float2(acc[fm][fn][0], acc[fm][fn][1]);
                *(float2*)&C[(size_t)(row + 8) * N + col] =
                    make_float2(acc[fm][fn][2], acc[fm][fn][3]);
            }
        }
    }
}

// ---------------------------------------------------------------------------
// Fused LayerNorm (width 256) + hi/lo pack.
// ---------------------------------------------------------------------------
__global__ __launch_bounds__(256) void ln256_pack(
    const float* __restrict__ X0, const float* __restrict__ X1,
    const float* __restrict__ g0, const float* __restrict__ b0,
    const float* __restrict__ g1, const float* __restrict__ b1,
    uint32_t* __restrict__ H0, uint32_t* __restrict__ L0,
    uint32_t* __restrict__ H1, uint32_t* __restrict__ L1)
{
    const int rr = blockIdx.x;
    const bool first = rr < T_TOK;
    const int row = first ? rr : rr - T_TOK;
    const float* X = first ? X0 : X1;
    const float* gg = first ? g0 : g1;
    const float* bb = first ? b0 : b1;
    uint32_t* H = first ? H0 : H1;
    uint32_t* L = first ? L0 : L1;

    const int tid = threadIdx.x;
    float v = X[(size_t)row * 256 + tid];

    __shared__ float red[8];
    float s = v;
#pragma unroll
    for (int m = 16; m > 0; m >>= 1) s += __shfl_xor_sync(0xffffffffu, s, m);
    if ((tid & 31) == 0) red[tid >> 5] = s;
    __syncthreads();
    float tot = 0.f;
#pragma unroll
    for (int i = 0; i < 8; i++) tot += red[i];
    const float mu = tot * (1.0f / 256.0f);
    const float d = v - mu;

    s = d * d;
    __syncthreads();
#pragma unroll
    for (int m = 16; m > 0; m >>= 1) s += __shfl_xor_sync(0xffffffffu, s, m);
    if ((tid & 31) == 0) red[tid >> 5] = s;
    __syncthreads();
    tot = 0.f;
#pragma unroll
    for (int i = 0; i < 8; i++) tot += red[i];
    const float var = tot * (1.0f / 256.0f);

    const float y = d * rsqrtf(var + 1e-5f) * gg[tid] + bb[tid];
    const float y2 = __shfl_down_sync(0xffffffffu, y, 1);
    if ((tid & 1) == 0) {
        uint32_t h, l;
        cvt_hilo2(y, y2, h, l);
        H[(size_t)row * 128 + (tid >> 1)] = h;
        L[(size_t)row * 128 + (tid >> 1)] = l;
    }
}

// ============================================================================
// attn_mma — all inputs pre-packed hi/lo. K staged by copy, Vt by byte_perm.
// Q scale (1/8) applied to S in fp32 post-MMA (exact).
// ============================================================================
#define ASTR 36
#define NEG_BIG (-1e30f)
#define KVW 1024   // words per token row of packed KV

__global__ __launch_bounds__(256) void attn_mma(
    const uint32_t* __restrict__ Qh, const uint32_t* __restrict__ Ql,
    const uint32_t* __restrict__ KVh, const uint32_t* __restrict__ KVl,
    uint32_t* __restrict__ AOh, uint32_t* __restrict__ AOl)
{
    __shared__ uint32_t Ksh[64 * ASTR], Ksl[64 * ASTR];
    __shared__ uint32_t Vth[64 * ASTR], Vtl[64 * ASTR];

    const int tid = threadIdx.x;
    const int warp = tid >> 5, lane = tid & 31;
    const int g = lane >> 2, t = lane & 3;
    const int qt = blockIdx.x, h = blockIdx.y, b = blockIdx.z;
    const int m0 = warp * 16;
    const size_t tokq = (size_t)b * SEQ + (size_t)qt * 128;

    // ldmatrix lane base offset for B-type fragments
    const int rowF = (lane & 7) + ((lane >> 4) * 8);
    const int colF = ((lane >> 3) & 1) * 4;
    const uint32_t offF = (uint32_t)(rowF * ASTR + colF) * 4u;
    const uint32_t aKh = smem_addr(Ksh) + offF, aKl = smem_addr(Ksl) + offF;
    const uint32_t aVh = smem_addr(Vth) + offF, aVl = smem_addr(Vtl) + offF;

    // ---- Q fragments straight from packed gmem ----
    uint32_t qh[4][4], ql[4][4];
    {
        const uint32_t* q0h = Qh + (tokq + m0 + g) * (DMODEL / 2) + h * (DH / 2);
        const uint32_t* q0l = Ql + (tokq + m0 + g) * (DMODEL / 2) + h * (DH / 2);
#pragma unroll
        for (int kc = 0; kc < 4; kc++) {
            const int w = kc * 8 + t;
            qh[kc][0] = q0h[w];
            qh[kc][1] = q0h[8 * (DMODEL / 2) + w];
            qh[kc][2] = q0h[w + 4];
            qh[kc][3] = q0h[8 * (DMODEL / 2) + w + 4];
            ql[kc][0] = q0l[w];
            ql[kc][1] = q0l[8 * (DMODEL / 2) + w];
            ql[kc][2] = q0l[w + 4];
            ql[kc][3] = q0l[8 * (DMODEL / 2) + w + 4];
        }
    }

    // V staging decomposition
    const int vdg = (tid & 7) * 4;    // input word group (4 words = 8 d)
    const int vtw = tid >> 3;         // token pair 0..31

    float oacc[8][4] = {};
    float m_0 = NEG_BIG, m_1 = NEG_BIG, l_0 = 0.f, l_1 = 0.f;

    const int nkt = 2 * qt + 2;
    for (int kt = 0; kt < nkt; kt++) {
        const size_t tokk = (size_t)b * SEQ + (size_t)kt * 64;
        __syncthreads();

        // ---- stage K: pure packed copy ----
        {
#pragma unroll
            for (int i = 0; i < 2; i++) {
                const int idx = i * 256 + tid;
                const int tok = idx >> 3, seg = idx & 7;
                const size_t gsrc = (tokk + tok) * KVW + h * 32 + seg * 4;
                *(uint4*)&Ksh[tok * ASTR + seg * 4] = *(const uint4*)&KVh[gsrc];
                *(uint4*)&Ksl[tok * ASTR + seg * 4] = *(const uint4*)&KVl[gsrc];
            }
        }
        // ---- stage V transposed via byte_perm ----
        {
            const size_t ga = (tokk + 2 * vtw) * KVW + 512 + h * 32 + vdg;
            const size_t gb = ga + KVW;
            uint4 Ahi = *(const uint4*)&KVh[ga];
            uint4 Bhi = *(const uint4*)&KVh[gb];
            uint4 Alo = *(const uint4*)&KVl[ga];
            uint4 Blo = *(const uint4*)&KVl[gb];
#pragma unroll
            for (int j = 0; j < 4; j++) {
                const uint32_t ah = (&Ahi.x)[j], bh = (&Bhi.x)[j];
                const uint32_t al = (&Alo.x)[j], bl = (&Blo.x)[j];
                const int d0 = 2 * (vdg + j);
                Vth[d0 * ASTR + vtw]       = __byte_perm(ah, bh, 0x5410);
                Vth[(d0 + 1) * ASTR + vtw] = __byte_perm(ah, bh, 0x7632);
                Vtl[d0 * ASTR + vtw]       = __byte_perm(al, bl, 0x5410);
                Vtl[(d0 + 1) * ASTR + vtw] = __byte_perm(al, bl, 0x7632);
            }
        }
        __syncthreads();

        if (kt * 64 > qt * 128 + m0 + 15) continue;

        // ---- S = Q K^T : 3-pass hi/lo ----
        float s[8][4] = {};
#pragma unroll
        for (int kc = 0; kc < 4; kc++) {
            const uint32_t kcoff = (uint32_t)(kc * 8) * 4u;
#pragma unroll
            for (int fnp = 0; fnp < 4; fnp++) {
                const uint32_t fo = (uint32_t)(fnp * 16 * ASTR) * 4u + kcoff;
                uint32_t h00, h01, h10, h11, l00, l01, l10, l11;
                ldsm_x4(h00, h01, h10, h11, aKh + fo);
                ldsm_x4(l00, l01, l10, l11, aKl + fo);
                float* sa = s[2 * fnp];
                float* sb = s[2 * fnp + 1];
                mma16816(sa, qh[kc][0], qh[kc][1], qh[kc][2], qh[kc][3], h00, h01);
                mma16816(sa, qh[kc][0], qh[kc][1], qh[kc][2], qh[kc][3], l00, l01);
                mma16816(sa, ql[kc][0], ql[kc][1], ql[kc][2], ql[kc][3], h00, h01);
                mma16816(sb, qh[kc][0], qh[kc][1], qh[kc][2], qh[kc][3], h10, h11);
                mma16816(sb, qh[kc][0], qh[kc][1], qh[kc][2], qh[kc][3], l10, l11);
                mma16816(sb, ql[kc][0], ql[kc][1], ql[kc][2], ql[kc][3], h10, h11);
            }
        }

        // ---- scale by 1/sqrt(DH)=0.125 (exact), then mask ----
#pragma unroll
        for (int fn = 0; fn < 8; fn++) {
            s[fn][0] *= 0.125f; s[fn][1] *= 0.125f;
            s[fn][2] *= 0.125f; s[fn][3] *= 0.125f;
        }

        if (kt >= 2 * qt) {
            const int r0 = qt * 128 + m0 + g;
            const int r1 = r0 + 8;
#pragma unroll
            for (int fn = 0; fn < 8; fn++) {
                const int c0 = kt * 64 + fn * 8 + 2 * t;
                if (c0 > r0)     s[fn][0] = NEG_BIG;
                if (c0 + 1 > r0) s[fn][1] = NEG_BIG;
                if (c0 > r1)     s[fn][2] = NEG_BIG;
                if (c0 + 1 > r1) s[fn][3] = NEG_BIG;
            }
        }

        float mx0 = s[0][0], mx1 = s[0][2];
#pragma unroll
        for (int fn = 0; fn < 8; fn++) {
            mx0 = fmaxf(mx0, fmaxf(s[fn][0], s[fn][1]));
            mx1 = fmaxf(mx1, fmaxf(s[fn][2], s[fn][3]));
        }
        mx0 = fmaxf(mx0, __shfl_xor_sync(0xffffffffu, mx0, 1));
        mx0 = fmaxf(mx0, __shfl_xor_sync(0xffffffffu, mx0, 2));
        mx1 = fmaxf(mx1, __shfl_xor_sync(0xffffffffu, mx1, 1));
        mx1 = fmaxf(mx1, __shfl_xor_sync(0xffffffffu, mx1, 2));

        const float mn0 = fmaxf(m_0, mx0), mn1 = fmaxf(m_1, mx1);
        const float cr0 = __expf(m_0 - mn0), cr1 = __expf(m_1 - mn1);
        m_0 = mn0; m_1 = mn1;

        float sum0 = 0.f, sum1 = 0.f;
#pragma unroll
        for (int fn = 0; fn < 8; fn++) {
            s[fn][0] = __expf(s[fn][0] - mn0);
            s[fn][1] = __expf(s[fn][1] - mn0);
            s[fn][2] = __expf(s[fn][2] - mn1);
            s[fn][3] = __expf(s[fn][3] - mn1);
            sum0 += s[fn][0] + s[fn][1];
            sum1 += s[fn][2] + s[fn][3];
        }
        sum0 += __shfl_xor_sync(0xffffffffu, sum0, 1);
        sum0 += __shfl_xor_sync(0xffffffffu, sum0, 2);
        sum1 += __shfl_xor_sync(0xffffffffu, sum1, 1);
        sum1 += __shfl_xor_sync(0xffffffffu, sum1, 2);
        l_0 = l_0 * cr0 + sum0;
        l_1 = l_1 * cr1 + sum1;

#pragma unroll
        for (int fn = 0; fn < 8; fn++) {
            oacc[fn][0] *= cr0; oacc[fn][1] *= cr0;
            oacc[fn][2] *= cr1; oacc[fn][3] *= cr1;
        }

        uint32_t ph[8], ph2[8], pl[8], pl2[8];
#pragma unroll
        for (int fn = 0; fn < 8; fn++) {
            cvt_hilo2(s[fn][0], s[fn][1], ph[fn],  pl[fn]);
            cvt_hilo2(s[fn][2], s[fn][3], ph2[fn], pl2[fn]);
        }

        // ---- O += P V : 3-pass hi/lo ----
#pragma unroll
        for (int kc = 0; kc < 4; kc++) {
            const uint32_t kcoff = (uint32_t)(kc * 8) * 4u;
            const uint32_t ah0 = ph[2 * kc],      ah1 = ph2[2 * kc];
            const uint32_t ah2 = ph[2 * kc + 1],  ah3 = ph2[2 * kc + 1];
            const uint32_t al0 = pl[2 * kc],      al1 = pl2[2 * kc];
            const uint32_t al2 = pl[2 * kc + 1],  al3 = pl2[2 * kc + 1];
#pragma unroll
            for (int fnp = 0; fnp < 4; fnp++) {
                const uint32_t fo = (uint32_t)(fnp * 16 * ASTR) * 4u + kcoff;
                uint32_t h00, h01, h10, h11, l00, l01, l10, l11;
                ldsm_x4(h00, h01, h10, h11, aVh + fo);
                ldsm_x4(l00, l01, l10, l11, aVl + fo);
                float* oa = oacc[2 * fnp];
                float* ob = oacc[2 * fnp + 1];
                mma16816(oa, ah0, ah1, ah2, ah3, h00, h01);
                mma16816(oa, ah0, ah1, ah2, ah3, l00, l01);
                mma16816(oa, al0, al1, al2, al3, h00, h01);
                mma16816(ob, ah0, ah1, ah2, ah3, h10, h11);
                mma16816(ob, ah0, ah1, ah2, ah3, l10, l11);
                mma16816(ob, al0, al1, al2, al3, h10, h11);
            }
        }
    }

    const float inv0 = 1.0f / l_0, inv1 = 1.0f / l_1;
    const size_t w0 = (tokq + m0 + g) * (DMODEL / 2) + h * (DH / 2);
    const size_t w1 = w0 + 8 * (DMODEL / 2);
#pragma unroll
    for (int fn = 0; fn < 8; fn++) {
        const int wi = fn * 4 + t;
        uint32_t hh, ll;
        cvt_hilo2(oacc[fn][0] * inv0, oacc[fn][1] * inv0, hh, ll);
        AOh[w0 + wi] = hh; AOl[w0 + wi] = ll;
        cvt_hilo2(oacc[fn][2] * inv1, oacc[fn][3] * inv1, hh, ll);
        AOh[w1 + wi] = hh; AOl[w1 + wi] = ll;
    }
}

// ---------------------------------------------------------------------------
// Launch
// ---------------------------------------------------------------------------
extern "C" void kernel_launch(void* const* d_in, const int* in_sizes, int n_in,
                              void* d_out, int out_size)
{
    const float* x     = (const float*)d_in[0];
    const float* W_dq  = (const float*)d_in[1];
    const float* W_uq  = (const float*)d_in[2];
    const float* q_g   = (const float*)d_in[3];
    const float* q_b   = (const float*)d_in[4];
    const float* W_dkv = (const float*)d_in[5];
    const float* W_ukv = (const float*)d_in[6];
    const float* kv_g  = (const float*)d_in[7];
    const float* kv_b  = (const float*)d_in[8];
    const float* W_o   = (const float*)d_in[9];
    float* out = (float*)d_out;

    uint32_t *xh, *xl, *wdqh, *wdql, *wdkh, *wdkl, *wuqh, *wuql, *wukh, *wukl, *woh, *wol;
    uint32_t *cqph, *cqpl, *ckph, *ckpl, *qph, *qpl, *kvh, *kvl, *aoh, *aol;
    float *cq, *ckv;
    cudaGetSymbolAddress((void**)&xh,   g_xh);   cudaGetSymbolAddress((void**)&xl,   g_xl);
    cudaGetSymbolAddress((void**)&wdqh, g_wdqh); cudaGetSymbolAddress((void**)&wdql, g_wdql);
    cudaGetSymbolAddress((void**)&wdkh, g_wdkh); cudaGetSymbolAddress((void**)&wdkl, g_wdkl);
    cudaGetSymbolAddress((void**)&wuqh, g_wuqh); cudaGetSymbolAddress((void**)&wuql, g_wuql);
    cudaGetSymbolAddress((void**)&wukh, g_wukh); cudaGetSymbolAddress((void**)&wukl, g_wukl);
    cudaGetSymbolAddress((void**)&woh,  g_woh);  cudaGetSymbolAddress((void**)&wol,  g_wol);
    cudaGetSymbolAddress((void**)&cq,   g_cq);   cudaGetSymbolAddress((void**)&ckv,  g_ckv);
    cudaGetSymbolAddress((void**)&cqph, g_cqph); cudaGetSymbolAddress((void**)&cqpl, g_cqpl);
    cudaGetSymbolAddress((void**)&ckph, g_ckph); cudaGetSymbolAddress((void**)&ckpl, g_ckpl);
    cudaGetSymbolAddress((void**)&qph,  g_qph);  cudaGetSymbolAddress((void**)&qpl,  g_qpl);
    cudaGetSymbolAddress((void**)&kvh,  g_kvh);  cudaGetSymbolAddress((void**)&kvl,  g_kvl);
    cudaGetSymbolAddress((void**)&aoh,  g_aoh);  cudaGetSymbolAddress((void**)&aol,  g_aol);

    cudaFuncSetAttribute(gemm_bf, cudaFuncAttributeMaxDynamicSharedMemorySize, GEMM_SMEM);

    // ---- pack inputs ----
    pack_hilo<<<(T_TOK * DMODEL / 2 + 255) / 256, 256>>>(x, xh, xl, T_TOK * DMODEL / 2);
    pack_hilo_t<<<(PROJ * (DMODEL / 2) + 255) / 256, 256>>>(W_dq,  wdqh, wdql, PROJ, DMODEL / 2);
    pack_hilo_t<<<(PROJ * (DMODEL / 2) + 255) / 256, 256>>>(W_dkv, wdkh, wdkl, PROJ, DMODEL / 2);
    pack_hilo_t<<<(DMODEL * (PROJ / 2) + 255) / 256, 256>>>(W_uq,  wuqh, wuql, DMODEL, PROJ / 2);
    pack_hilo_t<<<(2 * DMODEL * (PROJ / 2) + 255) / 256, 256>>>(W_ukv, wukh, wukl, 2 * DMODEL, PROJ / 2);
    pack_hilo<<<(DMODEL * DMODEL / 2 + 255) / 256, 256>>>(W_o, woh, wol, DMODEL * DMODEL / 2);

    // ---- fused down-projections (fp32 out): cq | ckv ----
    gemm_bf<<<dim3(4, T_TOK / 128), 256, GEMM_SMEM>>>(
        xh, xl, xh, xl, wdqh, wdql, wdkh, wdkl,
        cq, ckv, nullptr, nullptr, nullptr, nullptr,
        PROJ, PROJ, DMODEL / 2, 2, 0);

    // ---- fused LayerNorm + pack ----
    ln256_pack<<<2 * T_TOK, 256>>>(cq, ckv, q_g, q_b, kv_g, kv_b,
                                   cqph, cqpl, ckph, ckpl);

    // ---- fused up-projections (packed out): Q | KV ----
    gemm_bf<<<dim3(24, T_TOK / 128), 256, GEMM_SMEM>>>(
        cqph, cqpl, ckph, ckpl, wuqh, wuql, wukh, wukl,
        nullptr, nullptr, qph, qpl, kvh, kvl,
        DMODEL, 2 * DMODEL, PROJ / 2, 8, 1);

    // ---- attention (packed in, packed out) ----
    attn_mma<<<dim3(SEQ / 128, HEADS, BATCH), 256>>>(qph, qpl, kvh, kvl, aoh, aol);

    // ---- output projection: out = AO @ W_o^T (fp32 out) ----
    gemm_bf<<<dim3(8, T_TOK / 128), 256, GEMM_SMEM>>>(
        aoh, aol, aoh, aol, woh, wol, woh, wol,
        out, out, nullptr, nullptr, nullptr, nullptr,
        DMODEL, DMODEL, DMODEL / 2, 8, 0);
}

// round 13
// speedup vs baseline: 1.3302x; 1.3302x over previous
#include <cuda_runtime.h>
#include <cuda_fp16.h>
#include <math_constants.h>
#include <cstdint>

// Problem constants
#define BATCH   2
#define SEQ     2048
#define T_TOK   4096
#define DMODEL  1024
#define PROJ    256
#define HEADS   16
#define DH      64

// ---------------------------------------------------------------------------
// Scratch (device globals) — fp16 packed words (2 halves per u32)
// ---------------------------------------------------------------------------
__device__ uint32_t g_xh  [T_TOK * DMODEL / 2], g_xl [T_TOK * DMODEL / 2];
__device__ uint32_t g_wdq [PROJ * DMODEL / 2];          // [256][512] single
__device__ uint32_t g_wdk [PROJ * DMODEL / 2];
__device__ uint32_t g_wuq [DMODEL * PROJ / 2];          // [1024][128] single
__device__ uint32_t g_wuk [2 * DMODEL * PROJ / 2];      // [2048][128] single
__device__ uint32_t g_wo  [DMODEL * DMODEL / 2];        // [1024][512] single
__device__ float    g_cq  [T_TOK * PROJ];
__device__ float    g_ckv [T_TOK * PROJ];
__device__ uint32_t g_cqph[T_TOK * PROJ / 2], g_cqpl[T_TOK * PROJ / 2];
__device__ uint32_t g_ckph[T_TOK * PROJ / 2], g_ckpl[T_TOK * PROJ / 2];
__device__ uint32_t g_qph [T_TOK * DMODEL / 2], g_qpl[T_TOK * DMODEL / 2];
__device__ uint32_t g_kv  [T_TOK * DMODEL];             // [tok][1024] single (K|V)
__device__ uint32_t g_aoh [T_TOK * DMODEL / 2], g_aol[T_TOK * DMODEL / 2];

// ---------------------------------------------------------------------------
// Helpers
// ---------------------------------------------------------------------------
__device__ __forceinline__ void cvt_f16_hilo2(float x, float y, uint32_t& h, uint32_t& l)
{
    __half2 hv = __floats2half2_rn(x, y);     // .x = low half
    float2 hf = __half22float2(hv);
    __half2 lv = __floats2half2_rn(x - hf.x, y - hf.y);
    h = *(uint32_t*)&hv;
    l = *(uint32_t*)&lv;
}

__device__ __forceinline__ uint32_t cvt_f16_2(float x, float y)
{
    __half2 hv = __floats2half2_rn(x, y);
    return *(uint32_t*)&hv;
}

__device__ __forceinline__ void mma16816(float* c, uint32_t a0, uint32_t a1,
                                         uint32_t a2, uint32_t a3,
                                         uint32_t b0, uint32_t b1)
{
    asm volatile(
        "mma.sync.aligned.m16n8k16.row.col.f32.f16.f16.f32 "
        "{%0,%1,%2,%3}, {%4,%5,%6,%7}, {%8,%9}, {%0,%1,%2,%3};\n"
        : "+f"(c[0]), "+f"(c[1]), "+f"(c[2]), "+f"(c[3])
        : "r"(a0), "r"(a1), "r"(a2), "r"(a3), "r"(b0), "r"(b1));
}

__device__ __forceinline__ void ldsm_x4(uint32_t& r0, uint32_t& r1,
                                        uint32_t& r2, uint32_t& r3, uint32_t addr)
{
    asm volatile("ldmatrix.sync.aligned.m8n8.x4.shared.b16 {%0,%1,%2,%3}, [%4];"
                 : "=r"(r0), "=r"(r1), "=r"(r2), "=r"(r3) : "r"(addr));
}

__device__ __forceinline__ uint32_t smem_addr(const void* p)
{
    return (uint32_t)__cvta_generic_to_shared(p);
}

// ---------------------------------------------------------------------------
// Fused pack kernel: x split + 4 transposed weights single + W_o single.
// Block ranges: [0,8192) x | +512 wdq | +512 wdk | +512 wuq | +1024 wuk | +2048 wo
// ---------------------------------------------------------------------------
__device__ __forceinline__ void tpack(const float* __restrict__ W,
                                      uint32_t* __restrict__ P,
                                      int N, int Kw, int idx)
{
    const int kw = idx / N;
    const int n  = idx - kw * N;
    P[(size_t)n * Kw + kw] =
        cvt_f16_2(W[(size_t)(2 * kw) * N + n], W[(size_t)(2 * kw + 1) * N + n]);
}

__global__ __launch_bounds__(256) void pack_all(
    const float* __restrict__ x,    const float* __restrict__ wdq,
    const float* __restrict__ wdkv, const float* __restrict__ wuq,
    const float* __restrict__ wukv, const float* __restrict__ wo,
    uint32_t* __restrict__ xh, uint32_t* __restrict__ xl,
    uint32_t* __restrict__ pdq, uint32_t* __restrict__ pdk,
    uint32_t* __restrict__ puq, uint32_t* __restrict__ puk,
    uint32_t* __restrict__ pwo)
{
    const int bid = blockIdx.x, tid = threadIdx.x;
    if (bid < 8192) {                       // x hi/lo split
        const int i = bid * 256 + tid;
        float2 v = ((const float2*)x)[i];
        cvt_f16_hilo2(v.x, v.y, xh[i], xl[i]);
    } else if (bid < 8704) {
        tpack(wdq,  pdq, PROJ, DMODEL / 2, (bid - 8192) * 256 + tid);
    } else if (bid < 9216) {
        tpack(wdkv, pdk, PROJ, DMODEL / 2, (bid - 8704) * 256 + tid);
    } else if (bid < 9728) {
        tpack(wuq,  puq, DMODEL, PROJ / 2, (bid - 9216) * 256 + tid);
    } else if (bid < 10752) {
        tpack(wukv, puk, 2 * DMODEL, PROJ / 2, (bid - 9728) * 256 + tid);
    } else {                                // W_o straight single pack
        const int i = (bid - 10752) * 256 + tid;
        float2 v = ((const float2*)wo)[i];
        pwo[i] = cvt_f16_2(v.x, v.y);
    }
}
#define PACK_BLOCKS 12800

// ============================================================================
// gemm_f16: C = (Ah+Al)[M,K] @ B^T, A split fp16, B single fp16 (2 MMA passes).
// Tile 128x128, K-chunk 32 (16 words), 256 threads, single-buffered smem.
// Dual-side via halfx. pout: 0=fp32->C, 1=split->H,L, 2=single->H.
// ============================================================================
#define GSTR 20

__global__ __launch_bounds__(256) void gemm_f16(
    const uint32_t* __restrict__ A0h, const uint32_t* __restrict__ A0l,
    const uint32_t* __restrict__ A1h, const uint32_t* __restrict__ A1l,
    const uint32_t* __restrict__ B0,  const uint32_t* __restrict__ B1,
    float* __restrict__ C0, float* __restrict__ C1,
    uint32_t* __restrict__ H0, uint32_t* __restrict__ L0,
    uint32_t* __restrict__ H1,
    int N0, int N1, int Kw, int halfx, int pout0, int pout1)
{
    __shared__ uint32_t sAh[128 * GSTR], sAl[128 * GSTR], sB[128 * GSTR];

    const int tid  = threadIdx.x;
    const int warp = tid >> 5, lane = tid & 31;
    const int g = lane >> 2, t = lane & 3;
    const int mi = (warp & 1) * 64;
    const int ni = (warp >> 1) * 32;

    const bool s1 = blockIdx.x >= halfx;
    const uint32_t* Ah = s1 ? A1h : A0h;
    const uint32_t* Al = s1 ? A1l : A0l;
    const uint32_t* B  = s1 ? B1  : B0;
    float* C = s1 ? C1 : C0;
    uint32_t* H = s1 ? H1 : H0;
    const int N = s1 ? N1 : N0;
    const int pout = s1 ? pout1 : pout0;
    const int bn = (blockIdx.x - (s1 ? halfx : 0)) * 128;
    const int bm = blockIdx.y * 128;

    const int r0s = tid >> 2, s0s = tid & 3;
    const int r1s = (256 + tid) >> 2, s1s = (256 + tid) & 3;

    const uint32_t* pAh = Ah + (size_t)bm * Kw;
    const uint32_t* pAl = Al + (size_t)bm * Kw;
    const uint32_t* pB  = B  + (size_t)bn * Kw;

    // ldmatrix per-lane base byte offsets
    const int rowA = mi + (lane & 15);
    const int colA = (lane >> 4) * 4;
    const uint32_t offA = (uint32_t)(rowA * GSTR + colA) * 4u;
    const int rowB = ni + (lane & 7) + ((lane >> 4) * 8);
    const int colB = ((lane >> 3) & 1) * 4;
    const uint32_t offB = (uint32_t)(rowB * GSTR + colB) * 4u;
    const uint32_t aAh = smem_addr(sAh) + offA;
    const uint32_t aAl = smem_addr(sAl) + offA;
    const uint32_t aB  = smem_addr(sB)  + offB;

    uint4 rg[6];
    auto load_chunk = [&](int c) {
        const int kb = c * 16;
        rg[0] = *(const uint4*)&pAh[(size_t)r0s * Kw + kb + s0s * 4];
        rg[1] = *(const uint4*)&pAh[(size_t)r1s * Kw + kb + s1s * 4];
        rg[2] = *(const uint4*)&pAl[(size_t)r0s * Kw + kb + s0s * 4];
        rg[3] = *(const uint4*)&pAl[(size_t)r1s * Kw + kb + s1s * 4];
        rg[4] = *(const uint4*)&pB [(size_t)r0s * Kw + kb + s0s * 4];
        rg[5] = *(const uint4*)&pB [(size_t)r1s * Kw + kb + s1s * 4];
    };
    auto store_chunk = [&]() {
        *(uint4*)&sAh[r0s * GSTR + s0s * 4] = rg[0];
        *(uint4*)&sAh[r1s * GSTR + s1s * 4] = rg[1];
        *(uint4*)&sAl[r0s * GSTR + s0s * 4] = rg[2];
        *(uint4*)&sAl[r1s * GSTR + s1s * 4] = rg[3];
        *(uint4*)&sB [r0s * GSTR + s0s * 4] = rg[4];
        *(uint4*)&sB [r1s * GSTR + s1s * 4] = rg[5];
    };

    float acc[4][4][4] = {};

    const int nch = Kw / 16;
    load_chunk(0);
    for (int c = 0; c < nch; c++) {
        __syncthreads();
        store_chunk();
        __syncthreads();
        if (c + 1 < nch) load_chunk(c + 1);

#pragma unroll
        for (int k2 = 0; k2 < 2; k2++) {
            const uint32_t koff = (uint32_t)(k2 * 8) * 4u;
            uint32_t afh[4][4], afl[4][4];
#pragma unroll
            for (int fm = 0; fm < 4; fm++) {
                const uint32_t fo = (uint32_t)(fm * 16 * GSTR) * 4u + koff;
                ldsm_x4(afh[fm][0], afh[fm][1], afh[fm][2], afh[fm][3], aAh + fo);
                ldsm_x4(afl[fm][0], afl[fm][1], afl[fm][2], afl[fm][3], aAl + fo);
            }
            uint32_t bf[4][2];
#pragma unroll
            for (int fnp = 0; fnp < 2; fnp++) {
                const uint32_t fo = (uint32_t)(fnp * 16 * GSTR) * 4u + koff;
                ldsm_x4(bf[2 * fnp][0], bf[2 * fnp][1],
                        bf[2 * fnp + 1][0], bf[2 * fnp + 1][1], aB + fo);
            }
#pragma unroll
            for (int fm = 0; fm < 4; fm++)
#pragma unroll
                for (int fn = 0; fn < 4; fn++) {
                    mma16816(acc[fm][fn], afh[fm][0], afh[fm][1],
                             afh[fm][2], afh[fm][3], bf[fn][0], bf[fn][1]);
                    mma16816(acc[fm][fn], afl[fm][0], afl[fm][1],
                             afl[fm][2], afl[fm][3], bf[fn][0], bf[fn][1]);
                }
        }
    }

    if (pout == 1) {
        const int Nw = N >> 1;
#pragma unroll
        for (int fm = 0; fm < 4; fm++) {
            const int row = bm + mi + fm * 16 + g;
#pragma unroll
            for (int fn = 0; fn < 4; fn++) {
                const int wi = (bn + ni + fn * 8) / 2 + t;
                uint32_t hh, ll;
                cvt_f16_hilo2(acc[fm][fn][0], acc[fm][fn][1], hh, ll);
                H[(size_t)row * Nw + wi] = hh;
                L0[(size_t)row * Nw + wi] = ll;
                cvt_f16_hilo2(acc[fm][fn][2], acc[fm][fn][3], hh, ll);
                H[(size_t)(row + 8) * Nw + wi] = hh;
                L0[(size_t)(row + 8) * Nw + wi] = ll;
            }
        }
    } else if (pout == 2) {
        const int Nw = N >> 1;
#pragma unroll
        for (int fm = 0; fm < 4; fm++) {
            const int row = bm + mi + fm * 16 + g;
#pragma unroll
            for (int fn = 0; fn < 4; fn++) {
                const int wi = (bn + ni + fn * 8) / 2 + t;
                H[(size_t)row * Nw + wi] =
                    cvt_f16_2(acc[fm][fn][0], acc[fm][fn][1]);
                H[(size_t)(row + 8) * Nw + wi] =
                    cvt_f16_2(acc[fm][fn][2], acc[fm][fn][3]);
            }
        }
    } else {
#pragma unroll
        for (int fm = 0; fm < 4; fm++) {
            const int row = bm + mi + fm * 16 + g;
#pragma unroll
            for (int fn = 0; fn < 4; fn++) {
                const int col = bn + ni + fn * 8 + t * 2;
                *(float2*)&C[(size_t)row * N + col] =
                    make_float2(acc[fm][fn][0], acc[fm][fn][1]);
                *(float2*)&C[(size_t)(row + 8) * N + col] =
                    make_float2(acc[fm][fn][2], acc[fm][fn][3]);
            }
        }
    }
}

// ---------------------------------------------------------------------------
// Fused LayerNorm (width 256) + fp16 hi/lo pack.
// ---------------------------------------------------------------------------
__global__ __launch_bounds__(256) void ln256_pack(
    const float* __restrict__ X0, const float* __restrict__ X1,
    const float* __restrict__ g0, const float* __restrict__ b0,
    const float* __restrict__ g1, const float* __restrict__ b1,
    uint32_t* __restrict__ H0, uint32_t* __restrict__ L0,
    uint32_t* __restrict__ H1, uint32_t* __restrict__ L1)
{
    const int rr = blockIdx.x;
    const bool first = rr < T_TOK;
    const int row = first ? rr : rr - T_TOK;
    const float* X = first ? X0 : X1;
    const float* gg = first ? g0 : g1;
    const float* bb = first ? b0 : b1;
    uint32_t* H = first ? H0 : H1;
    uint32_t* L = first ? L0 : L1;

    const int tid = threadIdx.x;
    float v = X[(size_t)row * 256 + tid];

    __shared__ float red[8];
    float s = v;
#pragma unroll
    for (int m = 16; m > 0; m >>= 1) s += __shfl_xor_sync(0xffffffffu, s, m);
    if ((tid & 31) == 0) red[tid >> 5] = s;
    __syncthreads();
    float tot = 0.f;
#pragma unroll
    for (int i = 0; i < 8; i++) tot += red[i];
    const float mu = tot * (1.0f / 256.0f);
    const float d = v - mu;

    s = d * d;
    __syncthreads();
#pragma unroll
    for (int m = 16; m > 0; m >>= 1) s += __shfl_xor_sync(0xffffffffu, s, m);
    if ((tid & 31) == 0) red[tid >> 5] = s;
    __syncthreads();
    tot = 0.f;
#pragma unroll
    for (int i = 0; i < 8; i++) tot += red[i];
    const float var = tot * (1.0f / 256.0f);

    const float y = d * rsqrtf(var + 1e-5f) * gg[tid] + bb[tid];
    const float y2 = __shfl_down_sync(0xffffffffu, y, 1);
    if ((tid & 1) == 0) {
        uint32_t h, l;
        cvt_f16_hilo2(y, y2, h, l);
        H[(size_t)row * 128 + (tid >> 1)] = h;
        L[(size_t)row * 128 + (tid >> 1)] = l;
    }
}

// ============================================================================
// attn_mma — Q split fp16 (2-pass S), K/V single fp16; P split (2-pass PV).
// ============================================================================
#define ASTR 36
#define NEG_BIG (-1e30f)
#define KVW 1024   // words per token row of packed KV (K:0..511, V:512..1023)

__global__ __launch_bounds__(256) void attn_mma(
    const uint32_t* __restrict__ Qh, const uint32_t* __restrict__ Ql,
    const uint32_t* __restrict__ KV,
    uint32_t* __restrict__ AOh, uint32_t* __restrict__ AOl)
{
    __shared__ uint32_t Ks[64 * ASTR];
    __shared__ uint32_t Vt[64 * ASTR];

    const int tid = threadIdx.x;
    const int warp = tid >> 5, lane = tid & 31;
    const int g = lane >> 2, t = lane & 3;
    const int qt = blockIdx.x, h = blockIdx.y, b = blockIdx.z;
    const int m0 = warp * 16;
    const size_t tokq = (size_t)b * SEQ + (size_t)qt * 128;

    const int rowF = (lane & 7) + ((lane >> 4) * 8);
    const int colF = ((lane >> 3) & 1) * 4;
    const uint32_t offF = (uint32_t)(rowF * ASTR + colF) * 4u;
    const uint32_t aK = smem_addr(Ks) + offF;
    const uint32_t aV = smem_addr(Vt) + offF;

    // ---- Q fragments straight from packed gmem ----
    uint32_t qh[4][4], ql[4][4];
    {
        const uint32_t* q0h = Qh + (tokq + m0 + g) * (DMODEL / 2) + h * (DH / 2);
        const uint32_t* q0l = Ql + (tokq + m0 + g) * (DMODEL / 2) + h * (DH / 2);
#pragma unroll
        for (int kc = 0; kc < 4; kc++) {
            const int w = kc * 8 + t;
            qh[kc][0] = q0h[w];
            qh[kc][1] = q0h[8 * (DMODEL / 2) + w];
            qh[kc][2] = q0h[w + 4];
            qh[kc][3] = q0h[8 * (DMODEL / 2) + w + 4];
            ql[kc][0] = q0l[w];
            ql[kc][1] = q0l[8 * (DMODEL / 2) + w];
            ql[kc][2] = q0l[w + 4];
            ql[kc][3] = q0l[8 * (DMODEL / 2) + w + 4];
        }
    }

    const int vdg = (tid & 7) * 4;
    const int vtw = tid >> 3;

    float oacc[8][4] = {};
    float m_0 = NEG_BIG, m_1 = NEG_BIG, l_0 = 0.f, l_1 = 0.f;

    const int nkt = 2 * qt + 2;
    for (int kt = 0; kt < nkt; kt++) {
        const size_t tokk = (size_t)b * SEQ + (size_t)kt * 64;
        __syncthreads();

        // ---- stage K: pure packed copy ----
#pragma unroll
        for (int i = 0; i < 2; i++) {
            const int idx = i * 256 + tid;
            const int tok = idx >> 3, seg = idx & 7;
            *(uint4*)&Ks[tok * ASTR + seg * 4] =
                *(const uint4*)&KV[(tokk + tok) * KVW + h * 32 + seg * 4];
        }
        // ---- stage V transposed via byte_perm ----
        {
            const size_t ga = (tokk + 2 * vtw) * KVW + 512 + h * 32 + vdg;
            uint4 A = *(const uint4*)&KV[ga];
            uint4 B = *(const uint4*)&KV[ga + KVW];
#pragma unroll
            for (int j = 0; j < 4; j++) {
                const uint32_t a = (&A.x)[j], bb2 = (&B.x)[j];
                const int d0 = 2 * (vdg + j);
                Vt[d0 * ASTR + vtw]       = __byte_perm(a, bb2, 0x5410);
                Vt[(d0 + 1) * ASTR + vtw] = __byte_perm(a, bb2, 0x7632);
            }
        }
        __syncthreads();

        if (kt * 64 > qt * 128 + m0 + 15) continue;

        // ---- S = Q K^T : 2-pass (Qh, Ql) ----
        float s[8][4] = {};
#pragma unroll
        for (int kc = 0; kc < 4; kc++) {
            const uint32_t kcoff = (uint32_t)(kc * 8) * 4u;
#pragma unroll
            for (int fnp = 0; fnp < 4; fnp++) {
                const uint32_t fo = (uint32_t)(fnp * 16 * ASTR) * 4u + kcoff;
                uint32_t k00, k01, k10, k11;
                ldsm_x4(k00, k01, k10, k11, aK + fo);
                float* sa = s[2 * fnp];
                float* sb = s[2 * fnp + 1];
                mma16816(sa, qh[kc][0], qh[kc][1], qh[kc][2], qh[kc][3], k00, k01);
                mma16816(sa, ql[kc][0], ql[kc][1], ql[kc][2], ql[kc][3], k00, k01);
                mma16816(sb, qh[kc][0], qh[kc][1], qh[kc][2], qh[kc][3], k10, k11);
                mma16816(sb, ql[kc][0], ql[kc][1], ql[kc][2], ql[kc][3], k10, k11);
            }
        }

        // ---- scale (exact) then mask ----
#pragma unroll
        for (int fn = 0; fn < 8; fn++) {
            s[fn][0] *= 0.125f; s[fn][1] *= 0.125f;
            s[fn][2] *= 0.125f; s[fn][3] *= 0.125f;
        }

        if (kt >= 2 * qt) {
            const int r0 = qt * 128 + m0 + g;
            const int r1 = r0 + 8;
#pragma unroll
            for (int fn = 0; fn < 8; fn++) {
                const int c0 = kt * 64 + fn * 8 + 2 * t;
                if (c0 > r0)     s[fn][0] = NEG_BIG;
                if (c0 + 1 > r0) s[fn][1] = NEG_BIG;
                if (c0 > r1)     s[fn][2] = NEG_BIG;
                if (c0 + 1 > r1) s[fn][3] = NEG_BIG;
            }
        }

        float mx0 = s[0][0], mx1 = s[0][2];
#pragma unroll
        for (int fn = 0; fn < 8; fn++) {
            mx0 = fmaxf(mx0, fmaxf(s[fn][0], s[fn][1]));
            mx1 = fmaxf(mx1, fmaxf(s[fn][2], s[fn][3]));
        }
        mx0 = fmaxf(mx0, __shfl_xor_sync(0xffffffffu, mx0, 1));
        mx0 = fmaxf(mx0, __shfl_xor_sync(0xffffffffu, mx0, 2));
        mx1 = fmaxf(mx1, __shfl_xor_sync(0xffffffffu, mx1, 1));
        mx1 = fmaxf(mx1, __shfl_xor_sync(0xffffffffu, mx1, 2));

        const float mn0 = fmaxf(m_0, mx0), mn1 = fmaxf(m_1, mx1);
        const float cr0 = __expf(m_0 - mn0), cr1 = __expf(m_1 - mn1);
        m_0 = mn0; m_1 = mn1;

        float sum0 = 0.f, sum1 = 0.f;
#pragma unroll
        for (int fn = 0; fn < 8; fn++) {
            s[fn][0] = __expf(s[fn][0] - mn0);
            s[fn][1] = __expf(s[fn][1] - mn0);
            s[fn][2] = __expf(s[fn][2] - mn1);
            s[fn][3] = __expf(s[fn][3] - mn1);
            sum0 += s[fn][0] + s[fn][1];
            sum1 += s[fn][2] + s[fn][3];
        }
        sum0 += __shfl_xor_sync(0xffffffffu, sum0, 1);
        sum0 += __shfl_xor_sync(0xffffffffu, sum0, 2);
        sum1 += __shfl_xor_sync(0xffffffffu, sum1, 1);
        sum1 += __shfl_xor_sync(0xffffffffu, sum1, 2);
        l_0 = l_0 * cr0 + sum0;
        l_1 = l_1 * cr1 + sum1;

#pragma unroll
        for (int fn = 0; fn < 8; fn++) {
            oacc[fn][0] *= cr0; oacc[fn][1] *= cr0;
            oacc[fn][2] *= cr1; oacc[fn][3] *= cr1;
        }

        // ---- pack P split fp16 ----
        uint32_t ph[8], ph2[8], pl[8], pl2[8];
#pragma unroll
        for (int fn = 0; fn < 8; fn++) {
            cvt_f16_hilo2(s[fn][0], s[fn][1], ph[fn],  pl[fn]);
            cvt_f16_hilo2(s[fn][2], s[fn][3], ph2[fn], pl2[fn]);
        }

        // ---- O += P V : 2-pass (Ph, Pl) ----
#pragma unroll
        for (int kc = 0; kc < 4; kc++) {
            const uint32_t kcoff = (uint32_t)(kc * 8) * 4u;
            const uint32_t ah0 = ph[2 * kc],      ah1 = ph2[2 * kc];
            const uint32_t ah2 = ph[2 * kc + 1],  ah3 = ph2[2 * kc + 1];
            const uint32_t al0 = pl[2 * kc],      al1 = pl2[2 * kc];
            const uint32_t al2 = pl[2 * kc + 1],  al3 = pl2[2 * kc + 1];
#pragma unroll
            for (int fnp = 0; fnp < 4; fnp++) {
                const uint32_t fo = (uint32_t)(fnp * 16 * ASTR) * 4u + kcoff;
                uint32_t v00, v01, v10, v11;
                ldsm_x4(v00, v01, v10, v11, aV + fo);
                float* oa = oacc[2 * fnp];
                float* ob = oacc[2 * fnp + 1];
                mma16816(oa, ah0, ah1, ah2, ah3, v00, v01);
                mma16816(oa, al0, al1, al2, al3, v00, v01);
                mma16816(ob, ah0, ah1, ah2, ah3, v10, v11);
                mma16816(ob, al0, al1, al2, al3, v10, v11);
            }
        }
    }

    const float inv0 = 1.0f / l_0, inv1 = 1.0f / l_1;
    const size_t w0 = (tokq + m0 + g) * (DMODEL / 2) + h * (DH / 2);
    const size_t w1 = w0 + 8 * (DMODEL / 2);
#pragma unroll
    for (int fn = 0; fn < 8; fn++) {
        const int wi = fn * 4 + t;
        uint32_t hh, ll;
        cvt_f16_hilo2(oacc[fn][0] * inv0, oacc[fn][1] * inv0, hh, ll);
        AOh[w0 + wi] = hh; AOl[w0 + wi] = ll;
        cvt_f16_hilo2(oacc[fn][2] * inv1, oacc[fn][3] * inv1, hh, ll);
        AOh[w1 + wi] = hh; AOl[w1 + wi] = ll;
    }
}

// ---------------------------------------------------------------------------
// Launch
// ---------------------------------------------------------------------------
extern "C" void kernel_launch(void* const* d_in, const int* in_sizes, int n_in,
                              void* d_out, int out_size)
{
    const float* x     = (const float*)d_in[0];
    const float* W_dq  = (const float*)d_in[1];
    const float* W_uq  = (const float*)d_in[2];
    const float* q_g   = (const float*)d_in[3];
    const float* q_b   = (const float*)d_in[4];
    const float* W_dkv = (const float*)d_in[5];
    const float* W_ukv = (const float*)d_in[6];
    const float* kv_g  = (const float*)d_in[7];
    const float* kv_b  = (const float*)d_in[8];
    const float* W_o   = (const float*)d_in[9];
    float* out = (float*)d_out;

    uint32_t *xh, *xl, *pdq, *pdk, *puq, *puk, *pwo;
    uint32_t *cqph, *cqpl, *ckph, *ckpl, *qph, *qpl, *kv, *aoh, *aol;
    float *cq, *ckv;
    cudaGetSymbolAddress((void**)&xh,   g_xh);   cudaGetSymbolAddress((void**)&xl,   g_xl);
    cudaGetSymbolAddress((void**)&pdq,  g_wdq);  cudaGetSymbolAddress((void**)&pdk,  g_wdk);
    cudaGetSymbolAddress((void**)&puq,  g_wuq);  cudaGetSymbolAddress((void**)&puk,  g_wuk);
    cudaGetSymbolAddress((void**)&pwo,  g_wo);
    cudaGetSymbolAddress((void**)&cq,   g_cq);   cudaGetSymbolAddress((void**)&ckv,  g_ckv);
    cudaGetSymbolAddress((void**)&cqph, g_cqph); cudaGetSymbolAddress((void**)&cqpl, g_cqpl);
    cudaGetSymbolAddress((void**)&ckph, g_ckph); cudaGetSymbolAddress((void**)&ckpl, g_ckpl);
    cudaGetSymbolAddress((void**)&qph,  g_qph);  cudaGetSymbolAddress((void**)&qpl,  g_qpl);
    cudaGetSymbolAddress((void**)&kv,   g_kv);
    cudaGetSymbolAddress((void**)&aoh,  g_aoh);  cudaGetSymbolAddress((void**)&aol,  g_aol);

    // ---- single fused pack launch ----
    pack_all<<<PACK_BLOCKS, 256>>>(x, W_dq, W_dkv, W_uq, W_ukv, W_o,
                                   xh, xl, pdq, pdk, puq, puk, pwo);

    // ---- fused down-projections (fp32 out): cq | ckv ----
    gemm_f16<<<dim3(4, T_TOK / 128), 256>>>(
        xh, xl, xh, xl, pdq, pdk,
        cq, ckv, nullptr, nullptr, nullptr,
        PROJ, PROJ, DMODEL / 2, 2, 0, 0);

    // ---- fused LayerNorm + fp16 split pack ----
    ln256_pack<<<2 * T_TOK, 256>>>(cq, ckv, q_g, q_b, kv_g, kv_b,
                                   cqph, cqpl, ckph, ckpl);

    // ---- fused up-projections: Q (split out) | KV (single out) ----
    gemm_f16<<<dim3(24, T_TOK / 128), 256>>>(
        cqph, cqpl, ckph, ckpl, puq, puk,
        nullptr, nullptr, qph, qpl, kv,
        DMODEL, 2 * DMODEL, PROJ / 2, 8, 1, 2);

    // ---- attention ----
    attn_mma<<<dim3(SEQ / 128, HEADS, BATCH), 256>>>(qph, qpl, kv, aoh, aol);

    // ---- output projection: out = AO @ W_o^T (fp32 out) ----
    gemm_f16<<<dim3(8, T_TOK / 128), 256>>>(
        aoh, aol, aoh, aol, pwo, pwo,
        out, out, nullptr, nullptr, nullptr,
        DMODEL, DMODEL, DMODEL / 2, 8, 0, 0);
}

// round 16
// speedup vs baseline: 1.3692x; 1.0293x over previous
#include <cuda_runtime.h>
#include <cuda_fp16.h>
#include <math_constants.h>
#include <cstdint>

// Problem constants
#define BATCH   2
#define SEQ     2048
#define T_TOK   4096
#define DMODEL  1024
#define PROJ    256
#define HEADS   16
#define DH      64

// ---------------------------------------------------------------------------
// Scratch (device globals) — fp16 packed words (2 halves per u32)
// ---------------------------------------------------------------------------
__device__ uint32_t g_xh  [T_TOK * DMODEL / 2], g_xl [T_TOK * DMODEL / 2];
__device__ uint32_t g_wdq [PROJ * DMODEL / 2];
__device__ uint32_t g_wdk [PROJ * DMODEL / 2];
__device__ uint32_t g_wuq [DMODEL * PROJ / 2];
__device__ uint32_t g_wuk [2 * DMODEL * PROJ / 2];
__device__ uint32_t g_wo  [DMODEL * DMODEL / 2];
__device__ float    g_cq  [T_TOK * PROJ];
__device__ float    g_ckv [T_TOK * PROJ];
__device__ uint32_t g_cqph[T_TOK * PROJ / 2], g_cqpl[T_TOK * PROJ / 2];
__device__ uint32_t g_ckph[T_TOK * PROJ / 2], g_ckpl[T_TOK * PROJ / 2];
__device__ uint32_t g_qph [T_TOK * DMODEL / 2], g_qpl[T_TOK * DMODEL / 2];
__device__ uint32_t g_kv  [T_TOK * DMODEL];
__device__ uint32_t g_aoh [T_TOK * DMODEL / 2], g_aol[T_TOK * DMODEL / 2];

// ---------------------------------------------------------------------------
// Helpers
// ---------------------------------------------------------------------------
__device__ __forceinline__ void cvt_f16_hilo2(float x, float y, uint32_t& h, uint32_t& l)
{
    __half2 hv = __floats2half2_rn(x, y);     // .x = low half
    float2 hf = __half22float2(hv);
    __half2 lv = __floats2half2_rn(x - hf.x, y - hf.y);
    h = *(uint32_t*)&hv;
    l = *(uint32_t*)&lv;
}

__device__ __forceinline__ uint32_t cvt_f16_2(float x, float y)
{
    __half2 hv = __floats2half2_rn(x, y);
    return *(uint32_t*)&hv;
}

__device__ __forceinline__ void mma16816(float* c, uint32_t a0, uint32_t a1,
                                         uint32_t a2, uint32_t a3,
                                         uint32_t b0, uint32_t b1)
{
    asm volatile(
        "mma.sync.aligned.m16n8k16.row.col.f32.f16.f16.f32 "
        "{%0,%1,%2,%3}, {%4,%5,%6,%7}, {%8,%9}, {%0,%1,%2,%3};\n"
        : "+f"(c[0]), "+f"(c[1]), "+f"(c[2]), "+f"(c[3])
        : "r"(a0), "r"(a1), "r"(a2), "r"(a3), "r"(b0), "r"(b1));
}

__device__ __forceinline__ void ldsm_x4(uint32_t& r0, uint32_t& r1,
                                        uint32_t& r2, uint32_t& r3, uint32_t addr)
{
    asm volatile("ldmatrix.sync.aligned.m8n8.x4.shared.b16 {%0,%1,%2,%3}, [%4];"
                 : "=r"(r0), "=r"(r1), "=r"(r2), "=r"(r3) : "r"(addr));
}

__device__ __forceinline__ uint32_t smem_addr(const void* p)
{
    return (uint32_t)__cvta_generic_to_shared(p);
}

__device__ __forceinline__ void cp_async16(uint32_t saddr, const void* gptr)
{
    asm volatile("cp.async.cg.shared.global [%0], [%1], 16;"
                 :: "r"(saddr), "l"(gptr));
}
#define CP_COMMIT()  asm volatile("cp.async.commit_group;" ::: "memory")
#define CP_WAIT(n)   asm volatile("cp.async.wait_group %0;" :: "n"(n) : "memory")

// ---------------------------------------------------------------------------
// Fused pack kernel (unchanged from R13)
// ---------------------------------------------------------------------------
__device__ __forceinline__ void tpack(const float* __restrict__ W,
                                      uint32_t* __restrict__ P,
                                      int N, int Kw, int idx)
{
    const int kw = idx / N;
    const int n  = idx - kw * N;
    P[(size_t)n * Kw + kw] =
        cvt_f16_2(W[(size_t)(2 * kw) * N + n], W[(size_t)(2 * kw + 1) * N + n]);
}

__global__ __launch_bounds__(256) void pack_all(
    const float* __restrict__ x,    const float* __restrict__ wdq,
    const float* __restrict__ wdkv, const float* __restrict__ wuq,
    const float* __restrict__ wukv, const float* __restrict__ wo,
    uint32_t* __restrict__ xh, uint32_t* __restrict__ xl,
    uint32_t* __restrict__ pdq, uint32_t* __restrict__ pdk,
    uint32_t* __restrict__ puq, uint32_t* __restrict__ puk,
    uint32_t* __restrict__ pwo)
{
    const int bid = blockIdx.x, tid = threadIdx.x;
    if (bid < 8192) {
        const int i = bid * 256 + tid;
        float2 v = ((const float2*)x)[i];
        cvt_f16_hilo2(v.x, v.y, xh[i], xl[i]);
    } else if (bid < 8704) {
        tpack(wdq,  pdq, PROJ, DMODEL / 2, (bid - 8192) * 256 + tid);
    } else if (bid < 9216) {
        tpack(wdkv, pdk, PROJ, DMODEL / 2, (bid - 8704) * 256 + tid);
    } else if (bid < 9728) {
        tpack(wuq,  puq, DMODEL, PROJ / 2, (bid - 9216) * 256 + tid);
    } else if (bid < 10752) {
        tpack(wukv, puk, 2 * DMODEL, PROJ / 2, (bid - 9728) * 256 + tid);
    } else {
        const int i = (bid - 10752) * 256 + tid;
        float2 v = ((const float2*)wo)[i];
        pwo[i] = cvt_f16_2(v.x, v.y);
    }
}
#define PACK_BLOCKS 12800

// ============================================================================
// gemm_f16: C = (Ah+Al)[M,K] @ B^T, A split fp16, B single fp16, 2 MMA passes.
// cp.async 2-stage smem pipeline, 2 CTAs/SM target.
// ============================================================================
#define GSTR 20
#define GCH  (128 * GSTR)                 // words per array
#define GEMM_SMEM (2 * 3 * GCH * 4)       // 61440 bytes

__global__ __launch_bounds__(256, 2) void gemm_f16(
    const uint32_t* __restrict__ A0h, const uint32_t* __restrict__ A0l,
    const uint32_t* __restrict__ A1h, const uint32_t* __restrict__ A1l,
    const uint32_t* __restrict__ B0,  const uint32_t* __restrict__ B1,
    float* __restrict__ C0, float* __restrict__ C1,
    uint32_t* __restrict__ H0, uint32_t* __restrict__ L0,
    uint32_t* __restrict__ H1,
    int N0, int N1, int Kw, int halfx, int pout0, int pout1)
{
    extern __shared__ uint32_t sm[];

    const int tid  = threadIdx.x;
    const int warp = tid >> 5, lane = tid & 31;
    const int g = lane >> 2, t = lane & 3;
    const int mi = (warp & 1) * 64;
    const int ni = (warp >> 1) * 32;

    const bool s1 = blockIdx.x >= halfx;
    const uint32_t* Ah = s1 ? A1h : A0h;
    const uint32_t* Al = s1 ? A1l : A0l;
    const uint32_t* B  = s1 ? B1  : B0;
    float* C = s1 ? C1 : C0;
    uint32_t* H = s1 ? H1 : H0;
    const int N = s1 ? N1 : N0;
    const int pout = s1 ? pout1 : pout0;
    const int bn = (blockIdx.x - (s1 ? halfx : 0)) * 128;
    const int bm = blockIdx.y * 128;

    const int r0s = tid >> 2, s0s = tid & 3;
    const int r1s = (256 + tid) >> 2, s1s = (256 + tid) & 3;

    const uint32_t* pAh = Ah + (size_t)bm * Kw;
    const uint32_t* pAl = Al + (size_t)bm * Kw;
    const uint32_t* pB  = B  + (size_t)bn * Kw;

    const uint32_t base = smem_addr(sm);
    // per-thread cp.async smem byte offsets (stage 0)
    const uint32_t so0 = (uint32_t)(r0s * GSTR + s0s * 4) * 4u;
    const uint32_t so1 = (uint32_t)(r1s * GSTR + s1s * 4) * 4u;

    // ldmatrix per-lane base byte offsets (stage 0)
    const int rowA = mi + (lane & 15);
    const int colA = (lane >> 4) * 4;
    const uint32_t offA = (uint32_t)(rowA * GSTR + colA) * 4u;
    const int rowB = ni + (lane & 7) + ((lane >> 4) * 8);
    const int colB = ((lane >> 3) & 1) * 4;
    const uint32_t offB = (uint32_t)(rowB * GSTR + colB) * 4u;
    const uint32_t aAh = base + offA;
    const uint32_t aAl = base + (uint32_t)(GCH * 4) + offA;
    const uint32_t aB  = base + (uint32_t)(2 * GCH * 4) + offB;

    auto prefetch = [&](int c, int st) {
        const int kb = c * 16;
        const uint32_t sb = base + (uint32_t)st * (3u * GCH * 4u);
        cp_async16(sb + so0, &pAh[(size_t)r0s * Kw + kb + s0s * 4]);
        cp_async16(sb + so1, &pAh[(size_t)r1s * Kw + kb + s1s * 4]);
        cp_async16(sb + (uint32_t)(GCH * 4) + so0, &pAl[(size_t)r0s * Kw + kb + s0s * 4]);
        cp_async16(sb + (uint32_t)(GCH * 4) + so1, &pAl[(size_t)r1s * Kw + kb + s1s * 4]);
        cp_async16(sb + (uint32_t)(2 * GCH * 4) + so0, &pB[(size_t)r0s * Kw + kb + s0s * 4]);
        cp_async16(sb + (uint32_t)(2 * GCH * 4) + so1, &pB[(size_t)r1s * Kw + kb + s1s * 4]);
        CP_COMMIT();
    };

    float acc[4][4][4] = {};

    const int nch = Kw / 16;
    prefetch(0, 0);
    for (int c = 0; c < nch; c++) {
        const uint32_t stoff = (uint32_t)(c & 1) * (3u * GCH * 4u);
        if (c + 1 < nch) {
            prefetch(c + 1, (c + 1) & 1);
            CP_WAIT(1);                     // chunk c landed
        } else {
            CP_WAIT(0);
        }
        __syncthreads();

#pragma unroll
        for (int k2 = 0; k2 < 2; k2++) {
            const uint32_t koff = (uint32_t)(k2 * 8) * 4u + stoff;
            uint32_t afh[4][4], afl[4][4];
#pragma unroll
            for (int fm = 0; fm < 4; fm++) {
                const uint32_t fo = (uint32_t)(fm * 16 * GSTR) * 4u + koff;
                ldsm_x4(afh[fm][0], afh[fm][1], afh[fm][2], afh[fm][3], aAh + fo);
                ldsm_x4(afl[fm][0], afl[fm][1], afl[fm][2], afl[fm][3], aAl + fo);
            }
            uint32_t bf[4][2];
#pragma unroll
            for (int fnp = 0; fnp < 2; fnp++) {
                const uint32_t fo = (uint32_t)(fnp * 16 * GSTR) * 4u + koff;
                ldsm_x4(bf[2 * fnp][0], bf[2 * fnp][1],
                        bf[2 * fnp + 1][0], bf[2 * fnp + 1][1], aB + fo);
            }
#pragma unroll
            for (int fm = 0; fm < 4; fm++)
#pragma unroll
                for (int fn = 0; fn < 4; fn++) {
                    mma16816(acc[fm][fn], afh[fm][0], afh[fm][1],
                             afh[fm][2], afh[fm][3], bf[fn][0], bf[fn][1]);
                    mma16816(acc[fm][fn], afl[fm][0], afl[fm][1],
                             afl[fm][2], afl[fm][3], bf[fn][0], bf[fn][1]);
                }
        }
        __syncthreads();   // stage (c&1) free for prefetch(c+2) next iteration
    }

    if (pout == 1) {
        const int Nw = N >> 1;
#pragma unroll
        for (int fm = 0; fm < 4; fm++) {
            const int row = bm + mi + fm * 16 + g;
#pragma unroll
            for (int fn = 0; fn < 4; fn++) {
                const int wi = (bn + ni + fn * 8) / 2 + t;
                uint32_t hh, ll;
                cvt_f16_hilo2(acc[fm][fn][0], acc[fm][fn][1], hh, ll);
                H[(size_t)row * Nw + wi] = hh;
                L0[(size_t)row * Nw + wi] = ll;
                cvt_f16_hilo2(acc[fm][fn][2], acc[fm][fn][3], hh, ll);
                H[(size_t)(row + 8) * Nw + wi] = hh;
                L0[(size_t)(row + 8) * Nw + wi] = ll;
            }
        }
    } else if (pout == 2) {
        const int Nw = N >> 1;
#pragma unroll
        for (int fm = 0; fm < 4; fm++) {
            const int row = bm + mi + fm * 16 + g;
#pragma unroll
            for (int fn = 0; fn < 4; fn++) {
                const int wi = (bn + ni + fn * 8) / 2 + t;
                H[(size_t)row * Nw + wi] =
                    cvt_f16_2(acc[fm][fn][0], acc[fm][fn][1]);
                H[(size_t)(row + 8) * Nw + wi] =
                    cvt_f16_2(acc[fm][fn][2], acc[fm][fn][3]);
            }
        }
    } else {
#pragma unroll
        for (int fm = 0; fm < 4; fm++) {
            const int row = bm + mi + fm * 16 + g;
#pragma unroll
            for (int fn = 0; fn < 4; fn++) {
                const int col = bn + ni + fn * 8 + t * 2;
                *(float2*)&C[(size_t)row * N + col] =
                    make_float2(acc[fm][fn][0], acc[fm][fn][1]);
                *(float2*)&C[(size_t)(row + 8) * N + col] =
                    make_float2(acc[fm][fn][2], acc[fm][fn][3]);
            }
        }
    }
}

// ---------------------------------------------------------------------------
// Fused LayerNorm (width 256) + fp16 hi/lo pack (unchanged).
// ---------------------------------------------------------------------------
__global__ __launch_bounds__(256) void ln256_pack(
    const float* __restrict__ X0, const float* __restrict__ X1,
    const float* __restrict__ g0, const float* __restrict__ b0,
    const float* __restrict__ g1, const float* __restrict__ b1,
    uint32_t* __restrict__ H0, uint32_t* __restrict__ L0,
    uint32_t* __restrict__ H1, uint32_t* __restrict__ L1)
{
    const int rr = blockIdx.x;
    const bool first = rr < T_TOK;
    const int row = first ? rr : rr - T_TOK;
    const float* X = first ? X0 : X1;
    const float* gg = first ? g0 : g1;
    const float* bb = first ? b0 : b1;
    uint32_t* H = first ? H0 : H1;
    uint32_t* L = first ? L0 : L1;

    const int tid = threadIdx.x;
    float v = X[(size_t)row * 256 + tid];

    __shared__ float red[8];
    float s = v;
#pragma unroll
    for (int m = 16; m > 0; m >>= 1) s += __shfl_xor_sync(0xffffffffu, s, m);
    if ((tid & 31) == 0) red[tid >> 5] = s;
    __syncthreads();
    float tot = 0.f;
#pragma unroll
    for (int i = 0; i < 8; i++) tot += red[i];
    const float mu = tot * (1.0f / 256.0f);
    const float d = v - mu;

    s = d * d;
    __syncthreads();
#pragma unroll
    for (int m = 16; m > 0; m >>= 1) s += __shfl_xor_sync(0xffffffffu, s, m);
    if ((tid & 31) == 0) red[tid >> 5] = s;
    __syncthreads();
    tot = 0.f;
#pragma unroll
    for (int i = 0; i < 8; i++) tot += red[i];
    const float var = tot * (1.0f / 256.0f);

    const float y = d * rsqrtf(var + 1e-5f) * gg[tid] + bb[tid];
    const float y2 = __shfl_down_sync(0xffffffffu, y, 1);
    if ((tid & 1) == 0) {
        uint32_t h, l;
        cvt_f16_hilo2(y, y2, h, l);
        H[(size_t)row * 128 + (tid >> 1)] = h;
        L[(size_t)row * 128 + (tid >> 1)] = l;
    }
}

// ============================================================================
// attn_mma (unchanged from R13)
// ============================================================================
#define ASTR 36
#define NEG_BIG (-1e30f)
#define KVW 1024

__global__ __launch_bounds__(256) void attn_mma(
    const uint32_t* __restrict__ Qh, const uint32_t* __restrict__ Ql,
    const uint32_t* __restrict__ KV,
    uint32_t* __restrict__ AOh, uint32_t* __restrict__ AOl)
{
    __shared__ uint32_t Ks[64 * ASTR];
    __shared__ uint32_t Vt[64 * ASTR];

    const int tid = threadIdx.x;
    const int warp = tid >> 5, lane = tid & 31;
    const int g = lane >> 2, t = lane & 3;
    const int qt = blockIdx.x, h = blockIdx.y, b = blockIdx.z;
    const int m0 = warp * 16;
    const size_t tokq = (size_t)b * SEQ + (size_t)qt * 128;

    const int rowF = (lane & 7) + ((lane >> 4) * 8);
    const int colF = ((lane >> 3) & 1) * 4;
    const uint32_t offF = (uint32_t)(rowF * ASTR + colF) * 4u;
    const uint32_t aK = smem_addr(Ks) + offF;
    const uint32_t aV = smem_addr(Vt) + offF;

    uint32_t qh[4][4], ql[4][4];
    {
        const uint32_t* q0h = Qh + (tokq + m0 + g) * (DMODEL / 2) + h * (DH / 2);
        const uint32_t* q0l = Ql + (tokq + m0 + g) * (DMODEL / 2) + h * (DH / 2);
#pragma unroll
        for (int kc = 0; kc < 4; kc++) {
            const int w = kc * 8 + t;
            qh[kc][0] = q0h[w];
            qh[kc][1] = q0h[8 * (DMODEL / 2) + w];
            qh[kc][2] = q0h[w + 4];
            qh[kc][3] = q0h[8 * (DMODEL / 2) + w + 4];
            ql[kc][0] = q0l[w];
            ql[kc][1] = q0l[8 * (DMODEL / 2) + w];
            ql[kc][2] = q0l[w + 4];
            ql[kc][3] = q0l[8 * (DMODEL / 2) + w + 4];
        }
    }

    const int vdg = (tid & 7) * 4;
    const int vtw = tid >> 3;

    float oacc[8][4] = {};
    float m_0 = NEG_BIG, m_1 = NEG_BIG, l_0 = 0.f, l_1 = 0.f;

    const int nkt = 2 * qt + 2;
    for (int kt = 0; kt < nkt; kt++) {
        const size_t tokk = (size_t)b * SEQ + (size_t)kt * 64;
        __syncthreads();

#pragma unroll
        for (int i = 0; i < 2; i++) {
            const int idx = i * 256 + tid;
            const int tok = idx >> 3, seg = idx & 7;
            *(uint4*)&Ks[tok * ASTR + seg * 4] =
                *(const uint4*)&KV[(tokk + tok) * KVW + h * 32 + seg * 4];
        }
        {
            const size_t ga = (tokk + 2 * vtw) * KVW + 512 + h * 32 + vdg;
            uint4 A = *(const uint4*)&KV[ga];
            uint4 B = *(const uint4*)&KV[ga + KVW];
#pragma unroll
            for (int j = 0; j < 4; j++) {
                const uint32_t a = (&A.x)[j], bb2 = (&B.x)[j];
                const int d0 = 2 * (vdg + j);
                Vt[d0 * ASTR + vtw]       = __byte_perm(a, bb2, 0x5410);
                Vt[(d0 + 1) * ASTR + vtw] = __byte_perm(a, bb2, 0x7632);
            }
        }
        __syncthreads();

        if (kt * 64 > qt * 128 + m0 + 15) continue;

        float s[8][4] = {};
#pragma unroll
        for (int kc = 0; kc < 4; kc++) {
            const uint32_t kcoff = (uint32_t)(kc * 8) * 4u;
#pragma unroll
            for (int fnp = 0; fnp < 4; fnp++) {
                const uint32_t fo = (uint32_t)(fnp * 16 * ASTR) * 4u + kcoff;
                uint32_t k00, k01, k10, k11;
                ldsm_x4(k00, k01, k10, k11, aK + fo);
                float* sa = s[2 * fnp];
                float* sb = s[2 * fnp + 1];
                mma16816(sa, qh[kc][0], qh[kc][1], qh[kc][2], qh[kc][3], k00, k01);
                mma16816(sa, ql[kc][0], ql[kc][1], ql[kc][2], ql[kc][3], k00, k01);
                mma16816(sb, qh[kc][0], qh[kc][1], qh[kc][2], qh[kc][3], k10, k11);
                mma16816(sb, ql[kc][0], ql[kc][1], ql[kc][2], ql[kc][3], k10, k11);
            }
        }

#pragma unroll
        for (int fn = 0; fn < 8; fn++) {
            s[fn][0] *= 0.125f; s[fn][1] *= 0.125f;
            s[fn][2] *= 0.125f; s[fn][3] *= 0.125f;
        }

        if (kt >= 2 * qt) {
            const int r0 = qt * 128 + m0 + g;
            const int r1 = r0 + 8;
#pragma unroll
            for (int fn = 0; fn < 8; fn++) {
                const int c0 = kt * 64 + fn * 8 + 2 * t;
                if (c0 > r0)     s[fn][0] = NEG_BIG;
                if (c0 + 1 > r0) s[fn][1] = NEG_BIG;
                if (c0 > r1)     s[fn][2] = NEG_BIG;
                if (c0 + 1 > r1) s[fn][3] = NEG_BIG;
            }
        }

        float mx0 = s[0][0], mx1 = s[0][2];
#pragma unroll
        for (int fn = 0; fn < 8; fn++) {
            mx0 = fmaxf(mx0, fmaxf(s[fn][0], s[fn][1]));
            mx1 = fmaxf(mx1, fmaxf(s[fn][2], s[fn][3]));
        }
        mx0 = fmaxf(mx0, __shfl_xor_sync(0xffffffffu, mx0, 1));
        mx0 = fmaxf(mx0, __shfl_xor_sync(0xffffffffu, mx0, 2));
        mx1 = fmaxf(mx1, __shfl_xor_sync(0xffffffffu, mx1, 1));
        mx1 = fmaxf(mx1, __shfl_xor_sync(0xffffffffu, mx1, 2));

        const float mn0 = fmaxf(m_0, mx0), mn1 = fmaxf(m_1, mx1);
        const float cr0 = __expf(m_0 - mn0), cr1 = __expf(m_1 - mn1);
        m_0 = mn0; m_1 = mn1;

        float sum0 = 0.f, sum1 = 0.f;
#pragma unroll
        for (int fn = 0; fn < 8; fn++) {
            s[fn][0] = __expf(s[fn][0] - mn0);
            s[fn][1] = __expf(s[fn][1] - mn0);
            s[fn][2] = __expf(s[fn][2] - mn1);
            s[fn][3] = __expf(s[fn][3] - mn1);
            sum0 += s[fn][0] + s[fn][1];
            sum1 += s[fn][2] + s[fn][3];
        }
        sum0 += __shfl_xor_sync(0xffffffffu, sum0, 1);
        sum0 += __shfl_xor_sync(0xffffffffu, sum0, 2);
        sum1 += __shfl_xor_sync(0xffffffffu, sum1, 1);
        sum1 += __shfl_xor_sync(0xffffffffu, sum1, 2);
        l_0 = l_0 * cr0 + sum0;
        l_1 = l_1 * cr1 + sum1;

#pragma unroll
        for (int fn = 0; fn < 8; fn++) {
            oacc[fn][0] *= cr0; oacc[fn][1] *= cr0;
            oacc[fn][2] *= cr1; oacc[fn][3] *= cr1;
        }

        uint32_t ph[8], ph2[8], pl[8], pl2[8];
#pragma unroll
        for (int fn = 0; fn < 8; fn++) {
            cvt_f16_hilo2(s[fn][0], s[fn][1], ph[fn],  pl[fn]);
            cvt_f16_hilo2(s[fn][2], s[fn][3], ph2[fn], pl2[fn]);
        }

#pragma unroll
        for (int kc = 0; kc < 4; kc++) {
            const uint32_t kcoff = (uint32_t)(kc * 8) * 4u;
            const uint32_t ah0 = ph[2 * kc],      ah1 = ph2[2 * kc];
            const uint32_t ah2 = ph[2 * kc + 1],  ah3 = ph2[2 * kc + 1];
            const uint32_t al0 = pl[2 * kc],      al1 = pl2[2 * kc];
            const uint32_t al2 = pl[2 * kc + 1],  al3 = pl2[2 * kc + 1];
#pragma unroll
            for (int fnp = 0; fnp < 4; fnp++) {
                const uint32_t fo = (uint32_t)(fnp * 16 * ASTR) * 4u + kcoff;
                uint32_t v00, v01, v10, v11;
                ldsm_x4(v00, v01, v10, v11, aV + fo);
                float* oa = oacc[2 * fnp];
                float* ob = oacc[2 * fnp + 1];
                mma16816(oa, ah0, ah1, ah2, ah3, v00, v01);
                mma16816(oa, al0, al1, al2, al3, v00, v01);
                mma16816(ob, ah0, ah1, ah2, ah3, v10, v11);
                mma16816(ob, al0, al1, al2, al3, v10, v11);
            }
        }
    }

    const float inv0 = 1.0f / l_0, inv1 = 1.0f / l_1;
    const size_t w0 = (tokq + m0 + g) * (DMODEL / 2) + h * (DH / 2);
    const size_t w1 = w0 + 8 * (DMODEL / 2);
#pragma unroll
    for (int fn = 0; fn < 8; fn++) {
        const int wi = fn * 4 + t;
        uint32_t hh, ll;
        cvt_f16_hilo2(oacc[fn][0] * inv0, oacc[fn][1] * inv0, hh, ll);
        AOh[w0 + wi] = hh; AOl[w0 + wi] = ll;
        cvt_f16_hilo2(oacc[fn][2] * inv1, oacc[fn][3] * inv1, hh, ll);
        AOh[w1 + wi] = hh; AOl[w1 + wi] = ll;
    }
}

// ---------------------------------------------------------------------------
// Launch
// ---------------------------------------------------------------------------
extern "C" void kernel_launch(void* const* d_in, const int* in_sizes, int n_in,
                              void* d_out, int out_size)
{
    const float* x     = (const float*)d_in[0];
    const float* W_dq  = (const float*)d_in[1];
    const float* W_uq  = (const float*)d_in[2];
    const float* q_g   = (const float*)d_in[3];
    const float* q_b   = (const float*)d_in[4];
    const float* W_dkv = (const float*)d_in[5];
    const float* W_ukv = (const float*)d_in[6];
    const float* kv_g  = (const float*)d_in[7];
    const float* kv_b  = (const float*)d_in[8];
    const float* W_o   = (const float*)d_in[9];
    float* out = (float*)d_out;

    uint32_t *xh, *xl, *pdq, *pdk, *puq, *puk, *pwo;
    uint32_t *cqph, *cqpl, *ckph, *ckpl, *qph, *qpl, *kv, *aoh, *aol;
    float *cq, *ckv;
    cudaGetSymbolAddress((void**)&xh,   g_xh);   cudaGetSymbolAddress((void**)&xl,   g_xl);
    cudaGetSymbolAddress((void**)&pdq,  g_wdq);  cudaGetSymbolAddress((void**)&pdk,  g_wdk);
    cudaGetSymbolAddress((void**)&puq,  g_wuq);  cudaGetSymbolAddress((void**)&puk,  g_wuk);
    cudaGetSymbolAddress((void**)&pwo,  g_wo);
    cudaGetSymbolAddress((void**)&cq,   g_cq);   cudaGetSymbolAddress((void**)&ckv,  g_ckv);
    cudaGetSymbolAddress((void**)&cqph, g_cqph); cudaGetSymbolAddress((void**)&cqpl, g_cqpl);
    cudaGetSymbolAddress((void**)&ckph, g_ckph); cudaGetSymbolAddress((void**)&ckpl, g_ckpl);
    cudaGetSymbolAddress((void**)&qph,  g_qph);  cudaGetSymbolAddress((void**)&qpl,  g_qpl);
    cudaGetSymbolAddress((void**)&kv,   g_kv);
    cudaGetSymbolAddress((void**)&aoh,  g_aoh);  cudaGetSymbolAddress((void**)&aol,  g_aol);

    static int attr_set = 0;
    if (!attr_set) {
        cudaFuncSetAttribute(gemm_f16, cudaFuncAttributeMaxDynamicSharedMemorySize, GEMM_SMEM);
        attr_set = 1;
    }

    // ---- single fused pack launch ----
    pack_all<<<PACK_BLOCKS, 256>>>(x, W_dq, W_dkv, W_uq, W_ukv, W_o,
                                   xh, xl, pdq, pdk, puq, puk, pwo);

    // ---- fused down-projections (fp32 out): cq | ckv ----
    gemm_f16<<<dim3(4, T_TOK / 128), 256, GEMM_SMEM>>>(
        xh, xl, xh, xl, pdq, pdk,
        cq, ckv, nullptr, nullptr, nullptr,
        PROJ, PROJ, DMODEL / 2, 2, 0, 0);

    // ---- fused LayerNorm + fp16 split pack ----
    ln256_pack<<<2 * T_TOK, 256>>>(cq, ckv, q_g, q_b, kv_g, kv_b,
                                   cqph, cqpl, ckph, ckpl);

    // ---- fused up-projections: Q (split out) | KV (single out) ----
    gemm_f16<<<dim3(24, T_TOK / 128), 256, GEMM_SMEM>>>(
        cqph, cqpl, ckph, ckpl, puq, puk,
        nullptr, nullptr, qph, qpl, kv,
        DMODEL, 2 * DMODEL, PROJ / 2, 8, 1, 2);

    // ---- attention ----
    attn_mma<<<dim3(SEQ / 128, HEADS, BATCH), 256>>>(qph, qpl, kv, aoh, aol);

    // ---- output projection: out = AO @ W_o^T (fp32 out) ----
    gemm_f16<<<dim3(8, T_TOK / 128), 256, GEMM_SMEM>>>(
        aoh, aol, aoh, aol, pwo, pwo,
        out, out, nullptr, nullptr, nullptr,
        DMODEL, DMODEL, DMODEL / 2, 8, 0, 0);
}